// round 12
// baseline (speedup 1.0000x reference)
#include <cuda_runtime.h>
#include <cuda_fp16.h>

#define N_NODES 100000
#define N_EDGES 1600000
#define D 64
#define THREADS 256
#define NBLK (148 * 5)                              // co-resident via launch_bounds(256,5)
#define NTILE ((N_NODES + 511) / 512)               // 196 scan tiles of 512

// ---------------- packed f32x2 helpers (sm_103a) ------------------------------
#define PACK2(dst, lo, hi) \
    asm("mov.b64 %0, {%1, %2};" : "=l"(dst) : "f"(lo), "f"(hi))
#define UNPACK2(lo, hi, src) \
    asm("mov.b64 {%0, %1}, %2;" : "=f"(lo), "=f"(hi) : "l"(src))
#define FMA2(acc, a, b) \
    asm("fma.rn.f32x2 %0, %1, %2, %0;" : "+l"(acc) : "l"(a), "l"(b))

// ---------------- scratch (device globals; no allocation allowed) -------------
// INVARIANTS at every kernel_launch entry: g_cnt == 0, g_arrive == 0.
__device__ __align__(16)  int   g_cnt[N_NODES];
__device__ __align__(16)  float g_dinv[N_NODES];
__device__ __align__(16)  int2  g_csr[N_EDGES];      // (src, coeff) grouped by dst
__device__ __align__(16)  int   g_off[N_NODES];      // tile-LOCAL exclusive scan
__device__ __align__(16)  int   g_end[N_NODES];      // tile-LOCAL inclusive scan
__device__ __align__(16)  int   g_part[NTILE];       // scanned per-tile partials
__device__ __align__(128) uint2 g_xh [N_NODES * 16]; // x as fp16 (row = 128B)
__device__ __align__(128) uint2 g_h1h[N_NODES * 16]; // hop-1 result, fp16
__device__ __align__(128) float g_h2 [N_NODES * D];  // hop-2 result, fp32
__device__ int g_arrive;                             // reset by epilogue kernel

// ---------------- grid barrier (monotonic; no in-kernel reset) ----------------
__device__ __forceinline__ void grid_barrier(int target) {
    __syncthreads();
    if (threadIdx.x == 0) {
        __threadfence();
        atomicAdd(&g_arrive, 1);
        for (;;) {
            int v;
            asm volatile("ld.global.acquire.gpu.b32 %0, [%1];"
                         : "=r"(v) : "l"(&g_arrive));
            if (v >= target) break;
            __nanosleep(64);
        }
    }
    __syncthreads();
}

// ---------------- hop phase (round-7 inner loop, grid-stride outer) -----------
__device__ __forceinline__ void hop_phase(const uint2* __restrict__ in,
                                          void* __restrict__ outv,
                                          bool outHalf) {
    int widx = threadIdx.x >> 5;
    int lane = threadIdx.x & 31;
    int fl   = lane & 15;        // 8B slot within the 128B row
    int eh   = lane >> 4;        // which edge of the pair

    for (int warp = blockIdx.x * 8 + widx; warp < N_NODES; warp += NBLK * 8) {
        int blk = warp >> 9;
        int add = (blk > 0) ? g_part[blk - 1] : 0;
        int beg = g_off[warp] + add;
        int end = g_end[warp] + add;
        float di = g_dinv[warp];
        float sl = di * di;

        float2 accA = make_float2(0.f, 0.f);
        float2 accB = make_float2(0.f, 0.f);
        if (eh == 0) {           // self-loop term, counted once
            uint2 rs = __ldg(&in[warp * 16 + fl]);
            float2 s0 = __half22float2(*reinterpret_cast<const __half2*>(&rs.x));
            float2 s1 = __half22float2(*reinterpret_cast<const __half2*>(&rs.y));
            accA = make_float2(sl * s0.x, sl * s0.y);
            accB = make_float2(sl * s1.x, sl * s1.y);
        }

        #pragma unroll 4
        for (int e = beg + eh; e < end; e += 2) {
            int2 md = __ldg(&g_csr[e]);            // broadcast within half-warp
            float ci = __int_as_float(md.y);
            uint2 r = __ldg(&in[md.x * 16 + fl]);  // one 128B row per half-warp
            float2 lo = __half22float2(*reinterpret_cast<const __half2*>(&r.x));
            float2 hi = __half22float2(*reinterpret_cast<const __half2*>(&r.y));
            accA.x = fmaf(ci, lo.x, accA.x);
            accA.y = fmaf(ci, lo.y, accA.y);
            accB.x = fmaf(ci, hi.x, accB.x);
            accB.y = fmaf(ci, hi.y, accB.y);
        }

        accA.x += __shfl_xor_sync(0xffffffffu, accA.x, 16);
        accA.y += __shfl_xor_sync(0xffffffffu, accA.y, 16);
        accB.x += __shfl_xor_sync(0xffffffffu, accB.x, 16);
        accB.y += __shfl_xor_sync(0xffffffffu, accB.y, 16);

        if (eh == 0) {
            if (outHalf) {
                uint2 o;
                *reinterpret_cast<__half2*>(&o.x) = __floats2half2_rn(accA.x, accA.y);
                *reinterpret_cast<__half2*>(&o.y) = __floats2half2_rn(accB.x, accB.y);
                ((uint2*)outv)[warp * 16 + fl] = o;
            } else {
                ((float4*)outv)[warp * 16 + fl] =
                    make_float4(accA.x, accA.y, accB.x, accB.y);
            }
        }
        if (outHalf && lane == 0) g_cnt[warp] = 0;   // restore invariant post-fill
    }
}

// ---------------- the persistent fused kernel ---------------------------------
__global__ void __launch_bounds__(THREADS, 5) k_fused(
        const void* __restrict__ eiv, const float2* __restrict__ x2) {
    __shared__ int s[512];
    __shared__ int s_is64;
    int tid = threadIdx.x;
    int bid = blockIdx.x;

    // ---- P0a: per-block dtype probe (int64 => all high words zero) ----
    if (tid < 32) {
        unsigned hi = ((const unsigned int*)eiv)[2 * tid + 1];
        unsigned ball = __ballot_sync(0xffffffffu, hi != 0u);
        if (tid == 0) s_is64 = (ball == 0u);
    }
    __syncthreads();
    bool is64 = (s_is64 != 0);

    // ---- P0b: x -> fp16 ----
    for (int t = bid * THREADS + tid; t < N_NODES * 32; t += NBLK * THREADS) {
        float2 v = __ldg(&x2[t]);
        ((__half2*)g_xh)[t] = __floats2half2_rn(v.x, v.y);
    }
    // ---- P0c: in-degree histogram (g_cnt pre-zeroed, invariant) ----
    for (int e = bid * THREADS + tid; e < N_EDGES; e += NBLK * THREADS) {
        int d;
        if (is64) d = (int)((const long long*)eiv)[N_EDGES + e];
        else      d = ((const int*)eiv)[N_EDGES + e];
        atomicAdd(&g_cnt[d], 1);
    }
    grid_barrier(1 * NBLK);

    // ---- P1: per-tile scan of 512 counts; dinv; re-zero g_cnt ----
    for (int tile = bid; tile < NTILE; tile += NBLK) {
        int base = tile * 512;
        int i0 = base + tid, i1 = base + tid + 256;
        int v0 = (i0 < N_NODES) ? g_cnt[i0] : 0;
        int v1 = (i1 < N_NODES) ? g_cnt[i1] : 0;
        if (i0 < N_NODES) { g_dinv[i0] = rsqrtf((float)(v0 + 1)); g_cnt[i0] = 0; }
        if (i1 < N_NODES) { g_dinv[i1] = rsqrtf((float)(v1 + 1)); g_cnt[i1] = 0; }
        s[tid] = v0; s[tid + 256] = v1;
        __syncthreads();
        for (int off = 1; off < 512; off <<= 1) {
            int e0 = tid, e1 = tid + 256;
            int t0 = (e0 >= off) ? s[e0 - off] : 0;
            int t1 = (e1 >= off) ? s[e1 - off] : 0;
            __syncthreads();
            s[e0] += t0; s[e1] += t1;
            __syncthreads();
        }
        if (i0 < N_NODES) { g_end[i0] = s[tid];       g_off[i0] = s[tid] - v0; }
        if (i1 < N_NODES) { g_end[i1] = s[tid + 256]; g_off[i1] = s[tid + 256] - v1; }
        if (tid == 0) g_part[tile] = s[511];
        __syncthreads();
    }
    grid_barrier(2 * NBLK);

    // ---- P2: block 0 scans the NTILE partials (196 <= 256) ----
    if (bid == 0) {
        int p = (tid < NTILE) ? g_part[tid] : 0;
        s[tid] = p;
        __syncthreads();
        for (int off = 1; off < 256; off <<= 1) {
            int t2 = (tid >= off) ? s[tid - off] : 0;
            __syncthreads();
            s[tid] += t2;
            __syncthreads();
        }
        if (tid < NTILE) g_part[tid] = s[tid];
    }
    grid_barrier(3 * NBLK);

    // ---- P3: CSR fill (prefix inline; g_cnt as cursor) ----
    for (int e = bid * THREADS + tid; e < N_EDGES; e += NBLK * THREADS) {
        int sN, dN;
        if (is64) {
            sN = (int)((const long long*)eiv)[e];
            dN = (int)((const long long*)eiv)[N_EDGES + e];
        } else {
            sN = ((const int*)eiv)[e];
            dN = ((const int*)eiv)[N_EDGES + e];
        }
        float c = g_dinv[sN] * g_dinv[dN];
        int blk = dN >> 9;
        int add = (blk > 0) ? g_part[blk - 1] : 0;
        int pos = g_off[dN] + add + atomicAdd(&g_cnt[dN], 1);
        g_csr[pos] = make_int2(sN, __float_as_int(c));
    }
    grid_barrier(4 * NBLK);

    // ---- P4: hop 1 (xh -> h1h fp16); re-zeroes g_cnt ----
    hop_phase((const uint2*)g_xh, (void*)g_h1h, true);
    grid_barrier(5 * NBLK);

    // ---- P5: hop 2 (h1h -> h2 fp32) ----
    hop_phase((const uint2*)g_h1h, (void*)g_h2, false);
    // kernel end = sync point before epilogue launch
}

// ---------------- epilogue: out = relu(h2 @ W^T + b); resets g_arrive ---------
__global__ void __launch_bounds__(128) k_linear_relu(
        const float* __restrict__ h, const float* __restrict__ W,
        const float* __restrict__ b, float* __restrict__ out) {
    if (blockIdx.x == 0 && threadIdx.x == 0) g_arrive = 0;  // restore invariant

    __shared__ float4 Ws4[D * 16];   // W[o][k] as float4 over k
    __shared__ float bs[D];
    for (int i = threadIdx.x; i < D * 16; i += blockDim.x)
        Ws4[i] = ((const float4*)W)[i];
    for (int i = threadIdx.x; i < D; i += blockDim.x) bs[i] = b[i];
    __syncthreads();

    int n = blockIdx.x * blockDim.x + threadIdx.x;
    if (n >= N_NODES) return;

    unsigned long long acc[D];
    #pragma unroll
    for (int o = 0; o < D; o++) PACK2(acc[o], bs[o], 0.0f);

    const float4* hr = (const float4*)(h + n * D);
    #pragma unroll 2
    for (int k4 = 0; k4 < 16; k4++) {
        float4 hv = hr[k4];
        unsigned long long h01, h23;
        PACK2(h01, hv.x, hv.y);
        PACK2(h23, hv.z, hv.w);
        #pragma unroll
        for (int o = 0; o < D; o++) {
            float4 w = Ws4[o * 16 + k4];
            unsigned long long w01, w23;
            PACK2(w01, w.x, w.y);
            PACK2(w23, w.z, w.w);
            FMA2(acc[o], h01, w01);
            FMA2(acc[o], h23, w23);
        }
    }
    float* orow = out + n * D;
    #pragma unroll
    for (int o = 0; o < D; o++) {
        float lo, hi;
        UNPACK2(lo, hi, acc[o]);
        orow[o] = fmaxf(lo + hi, 0.0f);
    }
}

// ---------------- launch ------------------------------------------------------
extern "C" void kernel_launch(void* const* d_in, const int* in_sizes, int n_in,
                              void* d_out, int out_size) {
    const float* x  = (const float*)d_in[0];   // [N, 64]
    const float* W  = (const float*)d_in[1];   // [64, 64]
    const float* b  = (const float*)d_in[2];   // [64]
    const void*  ei = d_in[3];                 // [2, E] int32 or int64
    float* out = (float*)d_out;                // [N, 64]

    void* h2p = nullptr;
    cudaGetSymbolAddress(&h2p, g_h2);

    k_fused<<<NBLK, THREADS>>>(ei, (const float2*)x);

    const int gLin = (N_NODES + 127) / 128;
    k_linear_relu<<<gLin, 128>>>((const float*)h2p, W, b, out);
}